// round 15
// baseline (speedup 1.0000x reference)
#include <cuda_runtime.h>
#include <cuda_fp16.h>
#include <math.h>
#include <stdint.h>

#define NN 20000
#define NE 320000
#define CZ 256
#define CE 64
#define NH 8
#define CO 32
#define DF 576          // 2*CZ + CE
#define HC 256          // NH*CO
#define LN_EPS 1e-5f

// ---------------- scratch (static device globals; no allocation) -------------
__device__ float   g_X   [(size_t)NN * 512];    // X' = x @ W'x (fp32)
__device__ float   g_P   [(size_t)NN * 512];    // P' = p @ W'p (fp32)
__device__ __half  g_wh  [(size_t)NE * 256];    // w = v * eg (fp16)
__device__ float   g_q   [(size_t)NN * HC];
__device__ float   g_sc  [(size_t)NE * NH];     // exp(score)
__device__ float   g_ssum[(size_t)NN * NH];
__device__ float   g_attn[(size_t)NN * HC];
__device__ __half  g_attnh[(size_t)NN * HC];
__device__ __half  g_hh  [(size_t)NN * 2 * CZ];
__device__ __half  g_WkvT[512 * DF];            // [c][j] = lw_j * W_jc (fp16)
__device__ float   g_c0  [512];                 // lb@W + bkv
__device__ float   g_c1  [512];                 // lw@W
__device__ __half  g_xh  [(size_t)NN * CZ];
__device__ __half  g_ph  [(size_t)NN * CZ];
__device__ __half  g_eah [(size_t)NE * CE];
__device__ float   g_sx[NN], g_qx[NN], g_sp[NN], g_qp[NN];
__device__ float   g_se[NE], g_qe[NE];
__device__ __half  g_wqT [HC * CZ];
__device__ __half  g_weT [HC * CE];
__device__ __half  g_w1T [2 * CZ * CZ];
__device__ __half  g_w2T [CZ * 2 * CZ];
__device__ float   g_zeros[512];                // static zero-init (never written)

// ---------------- conversion pass --------------------------------------------
__global__ void k_cvt(const float* __restrict__ src, __half* __restrict__ dst, int n4) {
    int i = blockIdx.x * blockDim.x + threadIdx.x;
    if (i >= n4) return;
    float4 v = ((const float4*)src)[i];
    __half2 a = __floats2half2_rn(v.x, v.y);
    __half2 b = __floats2half2_rn(v.z, v.w);
    uint2 o; o.x = *(unsigned*)&a; o.y = *(unsigned*)&b;
    ((uint2*)dst)[i] = o;
}

// ------------- all weight prep in one kernel ---------------------------------
__global__ void k_prepW(const float* __restrict__ Wk, const float* __restrict__ Wv,
                        const float* __restrict__ lw, const float* __restrict__ lb,
                        const float* __restrict__ bk, const float* __restrict__ bv,
                        const float* __restrict__ Wq, const float* __restrict__ We,
                        const float* __restrict__ W1, const float* __restrict__ W2) {
    int i = blockIdx.x * blockDim.x + threadIdx.x;
    if (i < DF * 512) {
        int j = i >> 9, c = i & 511;
        float w = (c < 256) ? Wk[j * 256 + c] : Wv[j * 256 + (c - 256)];
        g_WkvT[(size_t)c * DF + j] = __float2half_rn(lw[j] * w);
    }
    if (i < HC * CE) {          // weT[n][k] = We[k][n]
        int n = i >> 6, k = i & 63;
        g_weT[n * 64 + k] = __float2half_rn(We[k * 256 + n]);
    }
    if (i < CZ * HC) {          // wqT
        int n = i >> 8, k = i & 255;
        g_wqT[n * 256 + k] = __float2half_rn(Wq[k * 256 + n]);
    }
    if (i < 512 * 256) {        // w1T[n(512)][k(256)] = W1[k][n]
        int n = i >> 8, k = i & 255;
        g_w1T[n * 256 + k] = __float2half_rn(W1[k * 512 + n]);
    }
    if (i < 256 * 512) {        // w2T[n(256)][k(512)] = W2[k][n]
        int n = i >> 9, k = i & 511;
        g_w2T[n * 512 + k] = __float2half_rn(W2[k * 256 + n]);
    }
    if (i < 512) {              // c1 = lw@W, c0 = lb@W + bkv
        int c = i;
        float s1 = 0.f, s0 = 0.f;
        for (int j = 0; j < DF; j++) {
            float w = (c < 256) ? Wk[j * 256 + c] : Wv[j * 256 + (c - 256)];
            s1 += lw[j] * w;
            s0 += lb[j] * w;
        }
        g_c1[c] = s1;
        g_c0[c] = s0 + ((c < 256) ? bk[c] : bv[c - 256]);
    }
}

// ------------- node+edge prep: sums, sumsq, fp16 copies, zeroing -------------
__global__ void k_pre(const float* __restrict__ x, const float* __restrict__ p,
                      const float* __restrict__ ea) {
    size_t gid = (size_t)blockIdx.x * 256 + threadIdx.x;
    if (gid < (size_t)NN * HC) g_attn[gid] = 0.f;
    if (gid < (size_t)NN * NH) g_ssum[gid] = 0.f;
    int w = blockIdx.x * 8 + (threadIdx.x >> 5);
    int lane = threadIdx.x & 31;
    if (w < NN) {
        const float* xr = x + (size_t)w * CZ;
        const float* pr = p + (size_t)w * CZ;
        float sxv = 0.f, qxv = 0.f, spv = 0.f, qpv = 0.f;
#pragma unroll
        for (int i = 0; i < 8; i++) {
            int j = lane + 32 * i;
            float vx = xr[j], vp = pr[j];
            sxv += vx; qxv += vx * vx;
            spv += vp; qpv += vp * vp;
            g_xh[(size_t)w * CZ + j] = __float2half_rn(vx);
            g_ph[(size_t)w * CZ + j] = __float2half_rn(vp);
        }
#pragma unroll
        for (int o = 16; o; o >>= 1) {
            sxv += __shfl_xor_sync(~0u, sxv, o);
            qxv += __shfl_xor_sync(~0u, qxv, o);
            spv += __shfl_xor_sync(~0u, spv, o);
            qpv += __shfl_xor_sync(~0u, qpv, o);
        }
        if (lane == 0) { g_sx[w] = sxv; g_qx[w] = qxv; g_sp[w] = spv; g_qp[w] = qpv; }
    } else if (w < NN + NE) {
        int e = w - NN;
        const float* er = ea + (size_t)e * CE;
        float v0 = er[lane], v1 = er[lane + 32];
        float s = v0 + v1, q = v0 * v0 + v1 * v1;
        g_eah[(size_t)e * CE + lane]      = __float2half_rn(v0);
        g_eah[(size_t)e * CE + lane + 32] = __float2half_rn(v1);
#pragma unroll
        for (int o = 16; o; o >>= 1) {
            s += __shfl_xor_sync(~0u, s, o);
            q += __shfl_xor_sync(~0u, q, o);
        }
        if (lane == 0) { g_se[e] = s; g_qe[e] = q; }
    }
}

// ================= fp16 GEMM 128x128x64, ldmatrix + swizzle, 3-stage =========
#define HT_STAGE 8192
#define HGEMM_SMEM (6 * HT_STAGE * 2)

__device__ __forceinline__ void cp16g(unsigned dst, const void* src, int sz) {
    asm volatile("cp.async.cg.shared.global [%0], [%1], 16, %2;\n"
                 :: "r"(dst), "l"(src), "r"(sz));
}
__device__ __forceinline__ void ldsm4(unsigned& r0, unsigned& r1, unsigned& r2,
                                      unsigned& r3, unsigned addr) {
    asm volatile("ldmatrix.sync.aligned.m8n8.x4.shared.b16 {%0,%1,%2,%3}, [%4];"
                 : "=r"(r0), "=r"(r1), "=r"(r2), "=r"(r3) : "r"(addr));
}
__device__ __forceinline__ void mma16816(float* c, const unsigned* a, const unsigned* b) {
    asm volatile(
        "mma.sync.aligned.m16n8k16.row.col.f32.f16.f16.f32 "
        "{%0,%1,%2,%3}, {%4,%5,%6,%7}, {%8,%9}, {%0,%1,%2,%3};\n"
        : "+f"(c[0]), "+f"(c[1]), "+f"(c[2]), "+f"(c[3])
        : "r"(a[0]), "r"(a[1]), "r"(a[2]), "r"(a[3]), "r"(b[0]), "r"(b[1]));
}

__global__ __launch_bounds__(256, 2) void hgemm(
    const __half* __restrict__ A, int lda,
    const __half* __restrict__ Bt, int ldb,
    const float* __restrict__ bias, void* __restrict__ Cv,
    int M, int N, int K, int act) {
    extern __shared__ __half smh[];
    int tid = threadIdx.x;
    int lane = tid & 31, wid = tid >> 5;
    int bm = blockIdx.y * 128, bn = blockIdx.x * 128;
    int wm = (wid >> 1) * 32;
    int wn = (wid & 1) * 64;
    int lm = lane >> 2, lq = lane & 3;

    unsigned asBase = (unsigned)__cvta_generic_to_shared(smh);
    unsigned bsBase = asBase + 3 * HT_STAGE * 2;

    int l7 = lane & 7;
    int rowA = lane & 15;
    int kcA  = lane >> 4;
    int rowB = (lane & 7) + ((lane & 16) ? 8 : 0);
    int kcB  = (lane >> 3) & 1;

    float acc[2][8][4];
#pragma unroll
    for (int i = 0; i < 2; i++)
#pragma unroll
        for (int j = 0; j < 8; j++)
#pragma unroll
            for (int q = 0; q < 4; q++) acc[i][j][q] = 0.f;

    int KT = K >> 6;

    auto load_stage = [&](int s, int k0) {
#pragma unroll
        for (int t = 0; t < 4; t++) {
            int c = tid + t * 256;
            int row = c >> 3, kc = c & 7;
            int ok = (bm + row < M) ? 16 : 0;
            cp16g(asBase + s * (HT_STAGE * 2) + row * 128 + ((kc ^ (row & 7)) << 4),
                  A + (size_t)(bm + row) * lda + k0 + kc * 8, ok);
        }
#pragma unroll
        for (int t = 0; t < 4; t++) {
            int c = tid + t * 256;
            int row = c >> 3, kc = c & 7;
            cp16g(bsBase + s * (HT_STAGE * 2) + row * 128 + ((kc ^ (row & 7)) << 4),
                  Bt + (size_t)(bn + row) * ldb + k0 + kc * 8, 16);
        }
        asm volatile("cp.async.commit_group;\n");
    };

    load_stage(0, 0);
    if (KT > 1) load_stage(1, 64);

    for (int kt = 0; kt < KT; kt++) {
        if (kt + 1 < KT) { asm volatile("cp.async.wait_group 1;\n"); }
        else             { asm volatile("cp.async.wait_group 0;\n"); }
        __syncthreads();
        if (kt + 2 < KT) load_stage((kt + 2) % 3, (kt + 2) * 64);
        int stage = kt % 3;
        unsigned aOff = asBase + stage * (HT_STAGE * 2);
        unsigned bOff = bsBase + stage * (HT_STAGE * 2);
#pragma unroll
        for (int ks = 0; ks < 4; ks++) {
            int kc = ks * 2;
            unsigned af[2][4], bf[8][2];
#pragma unroll
            for (int mt = 0; mt < 2; mt++) {
                unsigned addr = aOff + (wm + mt * 16 + rowA) * 128 +
                                (((kc + kcA) ^ l7) << 4);
                ldsm4(af[mt][0], af[mt][1], af[mt][2], af[mt][3], addr);
            }
#pragma unroll
            for (int ntp = 0; ntp < 4; ntp++) {
                unsigned addr = bOff + (wn + ntp * 16 + rowB) * 128 +
                                (((kc + kcB) ^ l7) << 4);
                ldsm4(bf[2 * ntp][0], bf[2 * ntp][1],
                      bf[2 * ntp + 1][0], bf[2 * ntp + 1][1], addr);
            }
#pragma unroll
            for (int mt = 0; mt < 2; mt++)
#pragma unroll
                for (int nt = 0; nt < 8; nt++)
                    mma16816(acc[mt][nt], af[mt], bf[nt]);
        }
    }

#pragma unroll
    for (int mt = 0; mt < 2; mt++) {
        int r0 = bm + wm + mt * 16 + lm;
        int r1 = r0 + 8;
#pragma unroll
        for (int nt = 0; nt < 8; nt++) {
            int c = bn + wn + nt * 8 + lq * 2;
            float b0 = bias[c], b1 = bias[c + 1];
            float v0 = acc[mt][nt][0] + b0, v1 = acc[mt][nt][1] + b1;
            float v2 = acc[mt][nt][2] + b0, v3 = acc[mt][nt][3] + b1;
            if (act & 1) {
                v0 = v0 / (1.f + expf(-v0)); v1 = v1 / (1.f + expf(-v1));
                v2 = v2 / (1.f + expf(-v2)); v3 = v3 / (1.f + expf(-v3));
            }
            if (act & 2) {
                __half* C = (__half*)Cv;
                __half2 h0 = __floats2half2_rn(v0, v1);
                __half2 h1 = __floats2half2_rn(v2, v3);
                if (r0 < M) *(__half2*)(C + (size_t)r0 * N + c) = h0;
                if (r1 < M) *(__half2*)(C + (size_t)r1 * N + c) = h1;
            } else {
                float* C = (float*)Cv;
                if (r0 < M) *(float2*)(C + (size_t)r0 * N + c) = make_float2(v0, v1);
                if (r1 < M) *(float2*)(C + (size_t)r1 * N + c) = make_float2(v2, v3);
            }
        }
    }
}

// ======== fused: E'/eg MMA + LN-combine + scores + w=v*eg, per 128 edges =====
// smem layout (bytes)
#define FS_A   0                   // ea tile        16384
#define FS_B   16384               // B tile         16384
#define FS_E   32768               // Ebuf half 128x128  32768
#define FS_G   65536               // egbuf half 128x128 32768
#define FS_SC  98304               // score acc f32 128x8 4096
#define FS_C0  102400              // c0 f32 512     2048
#define FS_C1  104448              // c1 f32 512     2048
#define FS_S   106496              // s[128] int
#define FS_D   (106496 + 512)
#define FS_R   (106496 + 1024)
#define FS_A1  (106496 + 1536)
#define FUSED_SMEM (106496 + 2048) // 108544

__global__ __launch_bounds__(256, 2) void k_fused(const int* __restrict__ ei) {
    extern __shared__ char sm[];
    int tid = threadIdx.x, lane = tid & 31, wid = tid >> 5;
    int e0 = blockIdx.x * 128;

    float* c0s  = (float*)(sm + FS_C0);
    float* c1s  = (float*)(sm + FS_C1);
    float* sacc = (float*)(sm + FS_SC);
    int*   sS   = (int*)(sm + FS_S);
    int*   sD   = (int*)(sm + FS_D);
    float* sR   = (float*)(sm + FS_R);
    float* sA1  = (float*)(sm + FS_A1);
    __half* Ebuf  = (__half*)(sm + FS_E);
    __half* egbuf = (__half*)(sm + FS_G);

    c0s[tid] = g_c0[tid]; c0s[tid + 256] = g_c0[tid + 256];
    c1s[tid] = g_c1[tid]; c1s[tid + 256] = g_c1[tid + 256];
    sacc[tid] = 0.f; sacc[tid + 256] = 0.f; sacc[tid + 512] = 0.f; sacc[tid + 768] = 0.f;
    if (tid < 128) {
        int e = e0 + tid;
        int s = ei[e], d = ei[NE + e];
        sS[tid] = s; sD[tid] = d;
        float mu = (g_se[e] + g_sx[s] + g_sp[d]) * (1.f / 576.f);
        float ms = (g_qe[e] + g_qx[s] + g_qp[d]) * (1.f / 576.f);
        float rstd = rsqrtf(ms - mu * mu + LN_EPS);
        sR[tid] = rstd; sA1[tid] = -rstd * mu;
    }

    unsigned aB = (unsigned)__cvta_generic_to_shared(sm + FS_A);
    unsigned bB = (unsigned)__cvta_generic_to_shared(sm + FS_B);

    // A tile: 128 edges x 64 halves, swizzled
#pragma unroll
    for (int t = 0; t < 4; t++) {
        int c = tid + t * 256;
        int row = c >> 3, kc = c & 7;
        cp16g(aB + row * 128 + ((kc ^ (row & 7)) << 4),
              g_eah + (size_t)(e0 + row) * CE + kc * 8, 16);
    }
    asm volatile("cp.async.commit_group;\n");

    // fragment geometry (same as hgemm)
    int wm = (wid >> 1) * 32, wn = (wid & 1) * 64;
    int lm = lane >> 2, lq = lane & 3, l7 = lane & 7;
    int rowA = lane & 15, kcA = lane >> 4;
    int rowB = (lane & 7) + ((lane & 16) ? 8 : 0);
    int kcB = (lane >> 3) & 1;

    const __half* Bts[6] = { g_WkvT, g_WkvT + 128 * DF, g_weT,
                             g_WkvT + 256 * DF, g_weT + 128 * 64, g_WkvT + 384 * DF };
    const int ldbs[6]  = { DF, DF, 64, DF, 64, DF };
    const int types[6] = { 0, 0, 1, 2, 1, 2 };   // 0=k, 1=eg, 2=v
    const int bases[6] = { 0, 128, 0, 0, 128, 128 };

    for (int t6 = 0; t6 < 6; t6++) {
        const __half* Bt = Bts[t6];
        int ldb = ldbs[t6], type = types[t6], base = bases[t6];
        // load B tile
#pragma unroll
        for (int t = 0; t < 4; t++) {
            int c = tid + t * 256;
            int row = c >> 3, kc = c & 7;
            cp16g(bB + row * 128 + ((kc ^ (row & 7)) << 4),
                  Bt + (size_t)row * ldb + kc * 8, 16);
        }
        asm volatile("cp.async.commit_group;\n");
        asm volatile("cp.async.wait_group 0;\n");
        __syncthreads();

        float acc[2][8][4];
#pragma unroll
        for (int i = 0; i < 2; i++)
#pragma unroll
            for (int j = 0; j < 8; j++)
#pragma unroll
                for (int q = 0; q < 4; q++) acc[i][j][q] = 0.f;
#pragma unroll
        for (int ks = 0; ks < 4; ks++) {
            int kc = ks * 2;
            unsigned af[2][4], bf[8][2];
#pragma unroll
            for (int mt = 0; mt < 2; mt++) {
                unsigned addr = aB + (wm + mt * 16 + rowA) * 128 + (((kc + kcA) ^ l7) << 4);
                ldsm4(af[mt][0], af[mt][1], af[mt][2], af[mt][3], addr);
            }
#pragma unroll
            for (int ntp = 0; ntp < 4; ntp++) {
                unsigned addr = bB + (wn + ntp * 16 + rowB) * 128 + (((kc + kcB) ^ l7) << 4);
                ldsm4(bf[2 * ntp][0], bf[2 * ntp][1], bf[2 * ntp + 1][0], bf[2 * ntp + 1][1], addr);
            }
#pragma unroll
            for (int mt = 0; mt < 2; mt++)
#pragma unroll
                for (int nt = 0; nt < 8; nt++)
                    mma16816(acc[mt][nt], af[mt], bf[nt]);
        }
        // epilogue -> smem (fp16)
        __half* dbuf = (type == 1) ? egbuf : Ebuf;
#pragma unroll
        for (int mt = 0; mt < 2; mt++) {
            int r0 = wm + mt * 16 + lm, r1 = r0 + 8;
#pragma unroll
            for (int nt = 0; nt < 8; nt++) {
                int c = wn + nt * 8 + lq * 2;
                *(__half2*)(dbuf + r0 * 128 + c) = __floats2half2_rn(acc[mt][nt][0], acc[mt][nt][1]);
                *(__half2*)(dbuf + r1 * 128 + c) = __floats2half2_rn(acc[mt][nt][2], acc[mt][nt][3]);
            }
        }
        __syncthreads();

        if (type == 0) {            // k: combine + score partial
            for (int it = 0; it < 16; it++) {
                int row = it * 8 + wid;
                int s = sS[row], d = sD[row];
                float rstd = sR[row], a1 = sA1[row];
                int gch = base + lane * 4;
                uint2 eh = *(const uint2*)(Ebuf + row * 128 + lane * 4);
                float2 ea0 = __half22float2(*(const __half2*)&eh.x);
                float2 ea1 = __half22float2(*(const __half2*)&eh.y);
                float4 X = *(const float4*)(g_X + (size_t)s * 512 + gch);
                float4 P = *(const float4*)(g_P + (size_t)d * 512 + gch);
                float4 C1 = *(const float4*)(c1s + gch);
                float4 C0 = *(const float4*)(c0s + gch);
                float k0 = rstd * (ea0.x + X.x + P.x) + a1 * C1.x + C0.x;
                float k1 = rstd * (ea0.y + X.y + P.y) + a1 * C1.y + C0.y;
                float k2 = rstd * (ea1.x + X.z + P.z) + a1 * C1.z + C0.z;
                float k3 = rstd * (ea1.y + X.w + P.w) + a1 * C1.w + C0.w;
                float4 q = *(const float4*)(g_q + (size_t)s * 256 + gch);
                float part = q.x * k0 + q.y * k1 + q.z * k2 + q.w * k3;
                part += __shfl_xor_sync(~0u, part, 1);
                part += __shfl_xor_sync(~0u, part, 2);
                part += __shfl_xor_sync(~0u, part, 4);
                if ((lane & 7) == 0) sacc[row * 8 + (gch >> 5)] += part;
            }
            __syncthreads();
        } else if (type == 2) {     // v: combine + w = v*eg -> gmem
            for (int it = 0; it < 16; it++) {
                int row = it * 8 + wid;
                int s = sS[row], d = sD[row];
                float rstd = sR[row], a1 = sA1[row];
                int gch = 256 + base + lane * 4;
                uint2 eh = *(const uint2*)(Ebuf + row * 128 + lane * 4);
                float2 ea0 = __half22float2(*(const __half2*)&eh.x);
                float2 ea1 = __half22float2(*(const __half2*)&eh.y);
                float4 X = *(const float4*)(g_X + (size_t)s * 512 + gch);
                float4 P = *(const float4*)(g_P + (size_t)d * 512 + gch);
                float4 C1 = *(const float4*)(c1s + gch);
                float4 C0 = *(const float4*)(c0s + gch);
                float v0 = rstd * (ea0.x + X.x + P.x) + a1 * C1.x + C0.x;
                float v1 = rstd * (ea0.y + X.y + P.y) + a1 * C1.y + C0.y;
                float v2 = rstd * (ea1.x + X.z + P.z) + a1 * C1.z + C0.z;
                float v3 = rstd * (ea1.y + X.w + P.w) + a1 * C1.w + C0.w;
                uint2 gh = *(const uint2*)(egbuf + row * 128 + lane * 4);
                float2 g0 = __half22float2(*(const __half2*)&gh.x);
                float2 g1 = __half22float2(*(const __half2*)&gh.y);
                __half2 w0 = __floats2half2_rn(v0 * g0.x, v1 * g0.y);
                __half2 w1 = __floats2half2_rn(v2 * g1.x, v3 * g1.y);
                uint2 o; o.x = *(unsigned*)&w0; o.y = *(unsigned*)&w1;
                *(uint2*)(g_wh + (size_t)(e0 + row) * 256 + base + lane * 4) = o;
            }
            __syncthreads();
        }
        // type 1 (eg): nothing; epilogue already wrote egbuf, sync done
    }

    // finalize scores
    for (int it = 0; it < 16; it++) {
        int row = it * 8 + wid;
        if (lane < 8) {
            float ex = expf(sacc[row * 8 + lane] * 0.17677669529663687f);
            int e = e0 + row, s = sS[row];
            g_sc[(size_t)e * 8 + lane] = ex;
            atomicAdd(&g_ssum[(size_t)s * 8 + lane], ex);
        }
    }
}

// ---------------- scatter: m = alpha * w, vector reductions ------------------
__global__ __launch_bounds__(256) void k_scatter(const int* __restrict__ ei) {
    int e = (blockIdx.x * blockDim.x + threadIdx.x) >> 5;
    int lane = threadIdx.x & 31;
    if (e >= NE) return;
    int s = ei[e];
    int h = lane >> 2;
    float alpha = g_sc[(size_t)e * 8 + h] * __frcp_rn(g_ssum[(size_t)s * 8 + h]);
    const uint4 ww = *(const uint4*)(g_wh + (size_t)e * 256 + lane * 8);
    float2 w0 = __half22float2(*(const __half2*)&ww.x);
    float2 w1 = __half22float2(*(const __half2*)&ww.y);
    float2 w2 = __half22float2(*(const __half2*)&ww.z);
    float2 w3 = __half22float2(*(const __half2*)&ww.w);
    float m0 = alpha * w0.x, m1 = alpha * w0.y;
    float m2 = alpha * w1.x, m3 = alpha * w1.y;
    float m4 = alpha * w2.x, m5 = alpha * w2.y;
    float m6 = alpha * w3.x, m7 = alpha * w3.y;
    float* dst = g_attn + (size_t)s * 256 + lane * 8;
    asm volatile("red.global.add.v4.f32 [%0], {%1,%2,%3,%4};"
                 :: "l"(dst), "f"(m0), "f"(m1), "f"(m2), "f"(m3) : "memory");
    asm volatile("red.global.add.v4.f32 [%0], {%1,%2,%3,%4};"
                 :: "l"(dst + 4), "f"(m4), "f"(m5), "f"(m6), "f"(m7) : "memory");
}

// ---------------- launch -----------------------------------------------------
extern "C" void kernel_launch(void* const* d_in, const int* in_sizes, int n_in,
                              void* d_out, int out_size) {
    const float* x  = (const float*)d_in[0];
    const float* p  = (const float*)d_in[1];
    const float* ea = (const float*)d_in[2];
    const int*   ei = (const int*)  d_in[3];
    const float* lw = (const float*)d_in[4];
    const float* lb = (const float*)d_in[5];
    const float* Wq = (const float*)d_in[6];
    const float* bq = (const float*)d_in[7];
    const float* Wk = (const float*)d_in[8];
    const float* bk = (const float*)d_in[9];
    const float* Wv = (const float*)d_in[10];
    const float* bv = (const float*)d_in[11];
    const float* We = (const float*)d_in[12];
    const float* W1 = (const float*)d_in[13];
    const float* b1 = (const float*)d_in[14];
    const float* W2 = (const float*)d_in[15];
    const float* b2 = (const float*)d_in[16];
    float* out = (float*)d_out;

    void *pX, *pP, *pQ, *pAttn, *pAttnH, *pHh;
    void *pWkvT, *pXh, *pPh, *pWqT, *pW1T, *pW2T, *pZeros;
    cudaGetSymbolAddress(&pX,     g_X);
    cudaGetSymbolAddress(&pP,     g_P);
    cudaGetSymbolAddress(&pQ,     g_q);
    cudaGetSymbolAddress(&pAttn,  g_attn);
    cudaGetSymbolAddress(&pAttnH, g_attnh);
    cudaGetSymbolAddress(&pHh,    g_hh);
    cudaGetSymbolAddress(&pWkvT,  g_WkvT);
    cudaGetSymbolAddress(&pXh,    g_xh);
    cudaGetSymbolAddress(&pPh,    g_ph);
    cudaGetSymbolAddress(&pWqT,   g_wqT);
    cudaGetSymbolAddress(&pW1T,   g_w1T);
    cudaGetSymbolAddress(&pW2T,   g_w2T);
    cudaGetSymbolAddress(&pZeros, g_zeros);

    cudaFuncSetAttribute(hgemm, cudaFuncAttributeMaxDynamicSharedMemorySize, HGEMM_SMEM);
    cudaFuncSetAttribute(k_fused, cudaFuncAttributeMaxDynamicSharedMemorySize, FUSED_SMEM);

    // 1: prep nodes/edges (sums + fp16 copies + zero attn/ssum)
    k_pre<<<(NN + NE + 7) / 8, 256>>>(x, p, ea);
    // 2: all weight prep
    k_prepW<<<(DF * 512 + 255) / 256, 256>>>(Wk, Wv, lw, lb, bk, bv, Wq, We, W1, W2);
    // 3: q = x @ Wq + bq (fp32)
    {
        dim3 g(HC / 128, (NN + 127) / 128);
        hgemm<<<g, 256, HGEMM_SMEM>>>((const __half*)pXh, CZ,
                                      (const __half*)pWqT, CZ, bq, pQ, NN, HC, CZ, 0);
    }
    // 4,5: X' and P' (fp32)
    {
        dim3 g(512 / 128, (NN + 127) / 128);
        hgemm<<<g, 256, HGEMM_SMEM>>>((const __half*)pXh, CZ,
                                      (const __half*)pWkvT + 64, DF,
                                      (const float*)pZeros, pX, NN, 512, CZ, 0);
        hgemm<<<g, 256, HGEMM_SMEM>>>((const __half*)pPh, CZ,
                                      (const __half*)pWkvT + 320, DF,
                                      (const float*)pZeros, pP, NN, 512, CZ, 0);
    }
    // 6: fused edge kernel (profiled)
    k_fused<<<NE / 128, 256, FUSED_SMEM>>>(ei);
    // 7: scatter
    k_scatter<<<(NE * 32 + 255) / 256, 256>>>(ei);
    // 8: attn -> fp16
    k_cvt<<<(NN * HC / 4 + 255) / 256, 256>>>((const float*)pAttn, (__half*)pAttnH, NN * HC / 4);
    // 9,10: MLP
    {
        dim3 g1(512 / 128, (NN + 127) / 128);
        hgemm<<<g1, 256, HGEMM_SMEM>>>((const __half*)pAttnH, CZ,
                                       (const __half*)pW1T, CZ, b1, pHh, NN, 512, CZ, 3);
        dim3 g2(HC / 128, (NN + 127) / 128);
        hgemm<<<g2, 256, HGEMM_SMEM>>>((const __half*)pHh, 2 * CZ,
                                       (const __half*)pW2T, 2 * CZ, b2, out, NN, HC, 2 * CZ, 0);
    }
}

// round 16
// speedup vs baseline: 1.0774x; 1.0774x over previous
#include <cuda_runtime.h>
#include <cuda_fp16.h>
#include <math.h>
#include <stdint.h>

#define NN 20000
#define NE 320000
#define CZ 256
#define CE 64
#define NH 8
#define CO 32
#define DF 576          // 2*CZ + CE
#define HC 256          // NH*CO
#define LN_EPS 1e-5f

// ---------------- scratch (static device globals; no allocation) -------------
__device__ float   g_X   [(size_t)NN * 512];    // X' = x @ W'x (fp32)
__device__ float   g_P   [(size_t)NN * 512];    // P' = p @ W'p (fp32)
__device__ __half  g_EG  [(size_t)NE * 768];    // E'(512) | eg(256) fp16
__device__ __half  g_wh  [(size_t)NE * 256];    // w = v * eg (fp16)
__device__ float   g_q   [(size_t)NN * HC];
__device__ float   g_sc  [(size_t)NE * NH];     // exp(score)
__device__ float   g_ssum[(size_t)NN * NH];
__device__ float   g_attn[(size_t)NN * HC];
__device__ __half  g_attnh[(size_t)NN * HC];
__device__ __half  g_hh  [(size_t)NN * 2 * CZ];
__device__ __half  g_WkvT[512 * DF];            // [c][j] = lw_j * W_jc (fp16)
__device__ __half  g_BT  [768 * 64];            // rows 0-511: W'e-slice; 512-767: WeT
__device__ float   g_c0  [512];                 // lb@W + bkv
__device__ float   g_c1  [512];                 // lw@W
__device__ __half  g_xh  [(size_t)NN * CZ];
__device__ __half  g_ph  [(size_t)NN * CZ];
__device__ __half  g_eah [(size_t)NE * CE];
__device__ float   g_sx[NN], g_qx[NN], g_sp[NN], g_qp[NN];
__device__ float   g_se[NE], g_qe[NE];
__device__ __half  g_wqT [HC * CZ];
__device__ __half  g_w1T [2 * CZ * CZ];
__device__ __half  g_w2T [CZ * 2 * CZ];
__device__ float   g_zeros[768];                // static zero-init (never written)

// ---------------- conversion pass --------------------------------------------
__global__ void k_cvt(const float* __restrict__ src, __half* __restrict__ dst, int n4) {
    int i = blockIdx.x * blockDim.x + threadIdx.x;
    if (i >= n4) return;
    float4 v = ((const float4*)src)[i];
    __half2 a = __floats2half2_rn(v.x, v.y);
    __half2 b = __floats2half2_rn(v.z, v.w);
    uint2 o; o.x = *(unsigned*)&a; o.y = *(unsigned*)&b;
    ((uint2*)dst)[i] = o;
}

// ------------- all weight prep in one kernel ---------------------------------
__global__ void k_prepW(const float* __restrict__ Wk, const float* __restrict__ Wv,
                        const float* __restrict__ lw, const float* __restrict__ lb,
                        const float* __restrict__ bk, const float* __restrict__ bv,
                        const float* __restrict__ Wq, const float* __restrict__ We,
                        const float* __restrict__ W1, const float* __restrict__ W2) {
    int i = blockIdx.x * blockDim.x + threadIdx.x;
    if (i < DF * 512) {
        int j = i >> 9, c = i & 511;
        float w = (c < 256) ? Wk[j * 256 + c] : Wv[j * 256 + (c - 256)];
        g_WkvT[(size_t)c * DF + j] = __float2half_rn(lw[j] * w);
    }
    if (i < 768 * 64) {         // merged EG B: [r][k]
        int r = i >> 6, k = i & 63;
        float w;
        if (r < 256)      w = lw[k] * Wk[k * 256 + r];
        else if (r < 512) w = lw[k] * Wv[k * 256 + (r - 256)];
        else              w = We[k * 256 + (r - 512)];
        g_BT[i] = __float2half_rn(w);
    }
    if (i < CZ * HC) {          // wqT
        int n = i >> 8, k = i & 255;
        g_wqT[n * 256 + k] = __float2half_rn(Wq[k * 256 + n]);
    }
    if (i < 512 * 256) {        // w1T[n(512)][k(256)] = W1[k][n]
        int n = i >> 8, k = i & 255;
        g_w1T[n * 256 + k] = __float2half_rn(W1[k * 512 + n]);
    }
    if (i < 256 * 512) {        // w2T[n(256)][k(512)] = W2[k][n]
        int n = i >> 9, k = i & 511;
        g_w2T[n * 512 + k] = __float2half_rn(W2[k * 256 + n]);
    }
    if (i < 512) {              // c1 = lw@W, c0 = lb@W + bkv
        int c = i;
        float s1 = 0.f, s0 = 0.f;
        for (int j = 0; j < DF; j++) {
            float w = (c < 256) ? Wk[j * 256 + c] : Wv[j * 256 + (c - 256)];
            s1 += lw[j] * w;
            s0 += lb[j] * w;
        }
        g_c1[c] = s1;
        g_c0[c] = s0 + ((c < 256) ? bk[c] : bv[c - 256]);
    }
}

// ------------- node+edge prep: sums, sumsq, fp16 copies, zeroing -------------
__global__ void k_pre(const float* __restrict__ x, const float* __restrict__ p,
                      const float* __restrict__ ea) {
    size_t gid = (size_t)blockIdx.x * 256 + threadIdx.x;
    if (gid < (size_t)NN * HC) g_attn[gid] = 0.f;
    if (gid < (size_t)NN * NH) g_ssum[gid] = 0.f;
    int w = blockIdx.x * 8 + (threadIdx.x >> 5);
    int lane = threadIdx.x & 31;
    if (w < NN) {
        const float* xr = x + (size_t)w * CZ;
        const float* pr = p + (size_t)w * CZ;
        float sxv = 0.f, qxv = 0.f, spv = 0.f, qpv = 0.f;
#pragma unroll
        for (int i = 0; i < 8; i++) {
            int j = lane + 32 * i;
            float vx = xr[j], vp = pr[j];
            sxv += vx; qxv += vx * vx;
            spv += vp; qpv += vp * vp;
            g_xh[(size_t)w * CZ + j] = __float2half_rn(vx);
            g_ph[(size_t)w * CZ + j] = __float2half_rn(vp);
        }
#pragma unroll
        for (int o = 16; o; o >>= 1) {
            sxv += __shfl_xor_sync(~0u, sxv, o);
            qxv += __shfl_xor_sync(~0u, qxv, o);
            spv += __shfl_xor_sync(~0u, spv, o);
            qpv += __shfl_xor_sync(~0u, qpv, o);
        }
        if (lane == 0) { g_sx[w] = sxv; g_qx[w] = qxv; g_sp[w] = spv; g_qp[w] = qpv; }
    } else if (w < NN + NE) {
        int e = w - NN;
        const float* er = ea + (size_t)e * CE;
        float v0 = er[lane], v1 = er[lane + 32];
        float s = v0 + v1, q = v0 * v0 + v1 * v1;
        g_eah[(size_t)e * CE + lane]      = __float2half_rn(v0);
        g_eah[(size_t)e * CE + lane + 32] = __float2half_rn(v1);
#pragma unroll
        for (int o = 16; o; o >>= 1) {
            s += __shfl_xor_sync(~0u, s, o);
            q += __shfl_xor_sync(~0u, q, o);
        }
        if (lane == 0) { g_se[e] = s; g_qe[e] = q; }
    }
}

// ================= fp16 GEMM 128x128x64, ldmatrix + swizzle, 3-stage =========
#define HT_STAGE 8192
#define HGEMM_SMEM (6 * HT_STAGE * 2)

__device__ __forceinline__ void cp16g(unsigned dst, const void* src, int sz) {
    asm volatile("cp.async.cg.shared.global [%0], [%1], 16, %2;\n"
                 :: "r"(dst), "l"(src), "r"(sz));
}
__device__ __forceinline__ void ldsm4(unsigned& r0, unsigned& r1, unsigned& r2,
                                      unsigned& r3, unsigned addr) {
    asm volatile("ldmatrix.sync.aligned.m8n8.x4.shared.b16 {%0,%1,%2,%3}, [%4];"
                 : "=r"(r0), "=r"(r1), "=r"(r2), "=r"(r3) : "r"(addr));
}
__device__ __forceinline__ void mma16816(float* c, const unsigned* a, const unsigned* b) {
    asm volatile(
        "mma.sync.aligned.m16n8k16.row.col.f32.f16.f16.f32 "
        "{%0,%1,%2,%3}, {%4,%5,%6,%7}, {%8,%9}, {%0,%1,%2,%3};\n"
        : "+f"(c[0]), "+f"(c[1]), "+f"(c[2]), "+f"(c[3])
        : "r"(a[0]), "r"(a[1]), "r"(a[2]), "r"(a[3]), "r"(b[0]), "r"(b[1]));
}

__global__ __launch_bounds__(256, 2) void hgemm(
    const __half* __restrict__ A, int lda,
    const __half* __restrict__ Bt, int ldb,
    const float* __restrict__ bias, void* __restrict__ Cv,
    int M, int N, int K, int act) {
    extern __shared__ __half smh[];
    int tid = threadIdx.x;
    int lane = tid & 31, wid = tid >> 5;
    int bm = blockIdx.y * 128, bn = blockIdx.x * 128;
    int wm = (wid >> 1) * 32;
    int wn = (wid & 1) * 64;
    int lm = lane >> 2, lq = lane & 3;

    unsigned asBase = (unsigned)__cvta_generic_to_shared(smh);
    unsigned bsBase = asBase + 3 * HT_STAGE * 2;

    int l7 = lane & 7;
    int rowA = lane & 15;
    int kcA  = lane >> 4;
    int rowB = (lane & 7) + ((lane & 16) ? 8 : 0);
    int kcB  = (lane >> 3) & 1;

    float acc[2][8][4];
#pragma unroll
    for (int i = 0; i < 2; i++)
#pragma unroll
        for (int j = 0; j < 8; j++)
#pragma unroll
            for (int q = 0; q < 4; q++) acc[i][j][q] = 0.f;

    int KT = K >> 6;

    auto load_stage = [&](int s, int k0) {
#pragma unroll
        for (int t = 0; t < 4; t++) {
            int c = tid + t * 256;
            int row = c >> 3, kc = c & 7;
            int ok = (bm + row < M) ? 16 : 0;
            cp16g(asBase + s * (HT_STAGE * 2) + row * 128 + ((kc ^ (row & 7)) << 4),
                  A + (size_t)(bm + row) * lda + k0 + kc * 8, ok);
        }
#pragma unroll
        for (int t = 0; t < 4; t++) {
            int c = tid + t * 256;
            int row = c >> 3, kc = c & 7;
            cp16g(bsBase + s * (HT_STAGE * 2) + row * 128 + ((kc ^ (row & 7)) << 4),
                  Bt + (size_t)(bn + row) * ldb + k0 + kc * 8, 16);
        }
        asm volatile("cp.async.commit_group;\n");
    };

    load_stage(0, 0);
    if (KT > 1) load_stage(1, 64);

    for (int kt = 0; kt < KT; kt++) {
        if (kt + 1 < KT) { asm volatile("cp.async.wait_group 1;\n"); }
        else             { asm volatile("cp.async.wait_group 0;\n"); }
        __syncthreads();
        if (kt + 2 < KT) load_stage((kt + 2) % 3, (kt + 2) * 64);
        int stage = kt % 3;
        unsigned aOff = asBase + stage * (HT_STAGE * 2);
        unsigned bOff = bsBase + stage * (HT_STAGE * 2);
#pragma unroll
        for (int ks = 0; ks < 4; ks++) {
            int kc = ks * 2;
            unsigned af[2][4], bf[8][2];
#pragma unroll
            for (int mt = 0; mt < 2; mt++) {
                unsigned addr = aOff + (wm + mt * 16 + rowA) * 128 +
                                (((kc + kcA) ^ l7) << 4);
                ldsm4(af[mt][0], af[mt][1], af[mt][2], af[mt][3], addr);
            }
#pragma unroll
            for (int ntp = 0; ntp < 4; ntp++) {
                unsigned addr = bOff + (wn + ntp * 16 + rowB) * 128 +
                                (((kc + kcB) ^ l7) << 4);
                ldsm4(bf[2 * ntp][0], bf[2 * ntp][1],
                      bf[2 * ntp + 1][0], bf[2 * ntp + 1][1], addr);
            }
#pragma unroll
            for (int mt = 0; mt < 2; mt++)
#pragma unroll
                for (int nt = 0; nt < 8; nt++)
                    mma16816(acc[mt][nt], af[mt], bf[nt]);
        }
    }

#pragma unroll
    for (int mt = 0; mt < 2; mt++) {
        int r0 = bm + wm + mt * 16 + lm;
        int r1 = r0 + 8;
#pragma unroll
        for (int nt = 0; nt < 8; nt++) {
            int c = bn + wn + nt * 8 + lq * 2;
            float b0 = bias[c], b1 = bias[c + 1];
            float v0 = acc[mt][nt][0] + b0, v1 = acc[mt][nt][1] + b1;
            float v2 = acc[mt][nt][2] + b0, v3 = acc[mt][nt][3] + b1;
            if (act & 1) {
                v0 = v0 / (1.f + expf(-v0)); v1 = v1 / (1.f + expf(-v1));
                v2 = v2 / (1.f + expf(-v2)); v3 = v3 / (1.f + expf(-v3));
            }
            if (act & 2) {
                __half* C = (__half*)Cv;
                __half2 h0 = __floats2half2_rn(v0, v1);
                __half2 h1 = __floats2half2_rn(v2, v3);
                if (r0 < M) *(__half2*)(C + (size_t)r0 * N + c) = h0;
                if (r1 < M) *(__half2*)(C + (size_t)r1 * N + c) = h1;
            } else {
                float* C = (float*)Cv;
                if (r0 < M) *(float2*)(C + (size_t)r0 * N + c) = make_float2(v0, v1);
                if (r1 < M) *(float2*)(C + (size_t)r1 * N + c) = make_float2(v2, v3);
            }
        }
    }
}

// ------- combine: LN reconstruction; scores inline; w = v*eg stored fp16 -----
// persistent: warp per edge, grid-stride. kv_c = rstd*(E'+X'+P')_c + a1*c1_c + c0_c
__global__ __launch_bounds__(256) void k_combine(const int* __restrict__ ei) {
    __shared__ float c0s[512], c1s[512];
    int tid = threadIdx.x;
    c0s[tid] = g_c0[tid]; c0s[tid + 256] = g_c0[tid + 256];
    c1s[tid] = g_c1[tid]; c1s[tid + 256] = g_c1[tid + 256];
    __syncthreads();
    int lane = tid & 31, wid = tid >> 5;
    int c = lane * 8;
    int stride = gridDim.x * 8;
    for (int e = blockIdx.x * 8 + wid; e < NE; e += stride) {
        int s = ei[e], d = ei[NE + e];
        float mu   = (g_se[e] + g_sx[s] + g_sp[d]) * (1.f / 576.f);
        float ms   = (g_qe[e] + g_qx[s] + g_qp[d]) * (1.f / 576.f);
        float rstd = rsqrtf(ms - mu * mu + LN_EPS);
        float a1   = -rstd * mu;
        const __half* EG = g_EG + (size_t)e * 768;
        // ---- k half (channels c..c+7): score only ----
        {
            uint4 eh = *(const uint4*)(EG + c);
            float2 e0 = __half22float2(*(const __half2*)&eh.x);
            float2 e1 = __half22float2(*(const __half2*)&eh.y);
            float2 e2 = __half22float2(*(const __half2*)&eh.z);
            float2 e3 = __half22float2(*(const __half2*)&eh.w);
            float4 xa = *(const float4*)(g_X + (size_t)s * 512 + c);
            float4 xb = *(const float4*)(g_X + (size_t)s * 512 + c + 4);
            float4 pa = *(const float4*)(g_P + (size_t)d * 512 + c);
            float4 pb = *(const float4*)(g_P + (size_t)d * 512 + c + 4);
            float4 c1a = *(const float4*)&c1s[c];
            float4 c1b = *(const float4*)&c1s[c + 4];
            float4 c0a = *(const float4*)&c0s[c];
            float4 c0b = *(const float4*)&c0s[c + 4];
            float k0 = rstd * (e0.x + xa.x + pa.x) + a1 * c1a.x + c0a.x;
            float k1 = rstd * (e0.y + xa.y + pa.y) + a1 * c1a.y + c0a.y;
            float k2 = rstd * (e1.x + xa.z + pa.z) + a1 * c1a.z + c0a.z;
            float k3 = rstd * (e1.y + xa.w + pa.w) + a1 * c1a.w + c0a.w;
            float k4 = rstd * (e2.x + xb.x + pb.x) + a1 * c1b.x + c0b.x;
            float k5 = rstd * (e2.y + xb.y + pb.y) + a1 * c1b.y + c0b.y;
            float k6 = rstd * (e3.x + xb.z + pb.z) + a1 * c1b.z + c0b.z;
            float k7 = rstd * (e3.y + xb.w + pb.w) + a1 * c1b.w + c0b.w;
            float4 qa = *(const float4*)(g_q + (size_t)s * 256 + c);
            float4 qb = *(const float4*)(g_q + (size_t)s * 256 + c + 4);
            float acc = qa.x * k0 + qa.y * k1 + qa.z * k2 + qa.w * k3 +
                        qb.x * k4 + qb.y * k5 + qb.z * k6 + qb.w * k7;
            acc += __shfl_xor_sync(~0u, acc, 1);
            acc += __shfl_xor_sync(~0u, acc, 2);
            if ((lane & 3) == 0) {
                int h = lane >> 2;
                float ex = expf(acc * 0.17677669529663687f);
                g_sc[(size_t)e * 8 + h] = ex;
                atomicAdd(&g_ssum[(size_t)s * 8 + h], ex);
            }
        }
        // ---- v half (channels 256+c..): w = v * eg -> fp16 ----
        {
            int c2 = 256 + c;
            uint4 eh = *(const uint4*)(EG + c2);
            float2 e0 = __half22float2(*(const __half2*)&eh.x);
            float2 e1 = __half22float2(*(const __half2*)&eh.y);
            float2 e2 = __half22float2(*(const __half2*)&eh.z);
            float2 e3 = __half22float2(*(const __half2*)&eh.w);
            float4 xa = *(const float4*)(g_X + (size_t)s * 512 + c2);
            float4 xb = *(const float4*)(g_X + (size_t)s * 512 + c2 + 4);
            float4 pa = *(const float4*)(g_P + (size_t)d * 512 + c2);
            float4 pb = *(const float4*)(g_P + (size_t)d * 512 + c2 + 4);
            float4 c1a = *(const float4*)&c1s[c2];
            float4 c1b = *(const float4*)&c1s[c2 + 4];
            float4 c0a = *(const float4*)&c0s[c2];
            float4 c0b = *(const float4*)&c0s[c2 + 4];
            float v0 = rstd * (e0.x + xa.x + pa.x) + a1 * c1a.x + c0a.x;
            float v1 = rstd * (e0.y + xa.y + pa.y) + a1 * c1a.y + c0a.y;
            float v2 = rstd * (e1.x + xa.z + pa.z) + a1 * c1a.z + c0a.z;
            float v3 = rstd * (e1.y + xa.w + pa.w) + a1 * c1a.w + c0a.w;
            float v4 = rstd * (e2.x + xb.x + pb.x) + a1 * c1b.x + c0b.x;
            float v5 = rstd * (e2.y + xb.y + pb.y) + a1 * c1b.y + c0b.y;
            float v6 = rstd * (e3.x + xb.z + pb.z) + a1 * c1b.z + c0b.z;
            float v7 = rstd * (e3.y + xb.w + pb.w) + a1 * c1b.w + c0b.w;
            uint4 gh = *(const uint4*)(EG + 512 + c);
            float2 g0 = __half22float2(*(const __half2*)&gh.x);
            float2 g1 = __half22float2(*(const __half2*)&gh.y);
            float2 g2 = __half22float2(*(const __half2*)&gh.z);
            float2 g3 = __half22float2(*(const __half2*)&gh.w);
            __half2 w0 = __floats2half2_rn(v0 * g0.x, v1 * g0.y);
            __half2 w1 = __floats2half2_rn(v2 * g1.x, v3 * g1.y);
            __half2 w2 = __floats2half2_rn(v4 * g2.x, v5 * g2.y);
            __half2 w3 = __floats2half2_rn(v6 * g3.x, v7 * g3.y);
            uint4 o;
            o.x = *(unsigned*)&w0; o.y = *(unsigned*)&w1;
            o.z = *(unsigned*)&w2; o.w = *(unsigned*)&w3;
            *(uint4*)(g_wh + (size_t)e * 256 + c) = o;
        }
    }
}

// ---------------- scatter: m = alpha * w, vector reductions ------------------
__global__ __launch_bounds__(256) void k_scatter(const int* __restrict__ ei) {
    int e = (blockIdx.x * blockDim.x + threadIdx.x) >> 5;
    int lane = threadIdx.x & 31;
    if (e >= NE) return;
    int s = ei[e];
    int h = lane >> 2;
    float alpha = g_sc[(size_t)e * 8 + h] * __frcp_rn(g_ssum[(size_t)s * 8 + h]);
    const uint4 ww = *(const uint4*)(g_wh + (size_t)e * 256 + lane * 8);
    float2 w0 = __half22float2(*(const __half2*)&ww.x);
    float2 w1 = __half22float2(*(const __half2*)&ww.y);
    float2 w2 = __half22float2(*(const __half2*)&ww.z);
    float2 w3 = __half22float2(*(const __half2*)&ww.w);
    float m0 = alpha * w0.x, m1 = alpha * w0.y;
    float m2 = alpha * w1.x, m3 = alpha * w1.y;
    float m4 = alpha * w2.x, m5 = alpha * w2.y;
    float m6 = alpha * w3.x, m7 = alpha * w3.y;
    float* dst = g_attn + (size_t)s * 256 + lane * 8;
    asm volatile("red.global.add.v4.f32 [%0], {%1,%2,%3,%4};"
                 :: "l"(dst), "f"(m0), "f"(m1), "f"(m2), "f"(m3) : "memory");
    asm volatile("red.global.add.v4.f32 [%0], {%1,%2,%3,%4};"
                 :: "l"(dst + 4), "f"(m4), "f"(m5), "f"(m6), "f"(m7) : "memory");
}

// ---------------- launch -----------------------------------------------------
extern "C" void kernel_launch(void* const* d_in, const int* in_sizes, int n_in,
                              void* d_out, int out_size) {
    const float* x  = (const float*)d_in[0];
    const float* p  = (const float*)d_in[1];
    const float* ea = (const float*)d_in[2];
    const int*   ei = (const int*)  d_in[3];
    const float* lw = (const float*)d_in[4];
    const float* lb = (const float*)d_in[5];
    const float* Wq = (const float*)d_in[6];
    const float* bq = (const float*)d_in[7];
    const float* Wk = (const float*)d_in[8];
    const float* bk = (const float*)d_in[9];
    const float* Wv = (const float*)d_in[10];
    const float* bv = (const float*)d_in[11];
    const float* We = (const float*)d_in[12];
    const float* W1 = (const float*)d_in[13];
    const float* b1 = (const float*)d_in[14];
    const float* W2 = (const float*)d_in[15];
    const float* b2 = (const float*)d_in[16];
    float* out = (float*)d_out;

    void *pX, *pP, *pEG, *pQ, *pAttn, *pAttnH, *pHh;
    void *pWkvT, *pBT, *pXh, *pPh, *pEah, *pWqT, *pW1T, *pW2T, *pZeros;
    cudaGetSymbolAddress(&pX,     g_X);
    cudaGetSymbolAddress(&pP,     g_P);
    cudaGetSymbolAddress(&pEG,    g_EG);
    cudaGetSymbolAddress(&pQ,     g_q);
    cudaGetSymbolAddress(&pAttn,  g_attn);
    cudaGetSymbolAddress(&pAttnH, g_attnh);
    cudaGetSymbolAddress(&pHh,    g_hh);
    cudaGetSymbolAddress(&pWkvT,  g_WkvT);
    cudaGetSymbolAddress(&pBT,    g_BT);
    cudaGetSymbolAddress(&pXh,    g_xh);
    cudaGetSymbolAddress(&pPh,    g_ph);
    cudaGetSymbolAddress(&pEah,   g_eah);
    cudaGetSymbolAddress(&pWqT,   g_wqT);
    cudaGetSymbolAddress(&pW1T,   g_w1T);
    cudaGetSymbolAddress(&pW2T,   g_w2T);
    cudaGetSymbolAddress(&pZeros, g_zeros);

    cudaFuncSetAttribute(hgemm, cudaFuncAttributeMaxDynamicSharedMemorySize, HGEMM_SMEM);

    // 1: prep nodes/edges (sums + fp16 copies + zero attn/ssum)
    k_pre<<<(NN + NE + 7) / 8, 256>>>(x, p, ea);
    // 2: all weight prep
    k_prepW<<<(DF * 512 + 255) / 256, 256>>>(Wk, Wv, lw, lb, bk, bv, Wq, We, W1, W2);
    // 3: q = x @ Wq + bq (fp32)
    {
        dim3 g(HC / 128, (NN + 127) / 128);
        hgemm<<<g, 256, HGEMM_SMEM>>>((const __half*)pXh, CZ,
                                      (const __half*)pWqT, CZ, bq, pQ, NN, HC, CZ, 0);
    }
    // 4,5: X' and P' (fp32)
    {
        dim3 g(512 / 128, (NN + 127) / 128);
        hgemm<<<g, 256, HGEMM_SMEM>>>((const __half*)pXh, CZ,
                                      (const __half*)pWkvT + 64, DF,
                                      (const float*)pZeros, pX, NN, 512, CZ, 0);
        hgemm<<<g, 256, HGEMM_SMEM>>>((const __half*)pPh, CZ,
                                      (const __half*)pWkvT + 320, DF,
                                      (const float*)pZeros, pP, NN, 512, CZ, 0);
    }
    // 6: merged EG = ea @ [W'e | We] (fp16 out, N=768)  -- profiled
    {
        dim3 g(768 / 128, NE / 128);
        hgemm<<<g, 256, HGEMM_SMEM>>>((const __half*)pEah, CE,
                                      (const __half*)pBT, CE,
                                      (const float*)pZeros, pEG, NE, 768, CE, 2);
    }
    // 7: combine (persistent): scores + w = v*eg
    k_combine<<<1184, 256>>>(ei);
    // 8: scatter
    k_scatter<<<(NE * 32 + 255) / 256, 256>>>(ei);
    // 9: attn -> fp16
    k_cvt<<<(NN * HC / 4 + 255) / 256, 256>>>((const float*)pAttn, (__half*)pAttnH, NN * HC / 4);
    // 10,11: MLP
    {
        dim3 g1(512 / 128, (NN + 127) / 128);
        hgemm<<<g1, 256, HGEMM_SMEM>>>((const __half*)pAttnH, CZ,
                                       (const __half*)pW1T, CZ, b1, pHh, NN, 512, CZ, 3);
        dim3 g2(HC / 128, (NN + 127) / 128);
        hgemm<<<g2, 256, HGEMM_SMEM>>>((const __half*)pHh, 2 * CZ,
                                       (const __half*)pW2T, 2 * CZ, b2, out, NN, HC, 2 * CZ, 0);
    }
}

// round 17
// speedup vs baseline: 1.1055x; 1.0261x over previous
#include <cuda_runtime.h>
#include <cuda_fp16.h>
#include <math.h>
#include <stdint.h>

#define NN 20000
#define NE 320000
#define CZ 256
#define CE 64
#define NH 8
#define CO 32
#define DF 576          // 2*CZ + CE
#define HC 256          // NH*CO
#define LN_EPS 1e-5f

// ---------------- scratch (static device globals; no allocation) -------------
__device__ float   g_X   [(size_t)NN * 512];    // X' = x @ W'x (fp32)
__device__ float   g_P   [(size_t)NN * 512];    // P' = p @ W'p (fp32)
__device__ __half  g_EG  [(size_t)NE * 768];    // E'(512) | eg(256) fp16
__device__ __half  g_wh  [(size_t)NE * 256];    // w = v * eg (fp16)
__device__ __half  g_qh  [(size_t)NN * HC];     // q fp16
__device__ float   g_QX  [(size_t)NN * NH];     // per-node per-head q.X' (k half)
__device__ float   g_QC1 [(size_t)NN * NH];     // q.c1 (k half)
__device__ float   g_QC0 [(size_t)NN * NH];     // q.c0 (k half)
__device__ float   g_sc  [(size_t)NE * NH];     // exp(score)
__device__ float   g_ssum[(size_t)NN * NH];
__device__ float   g_attn[(size_t)NN * HC];
__device__ __half  g_attnh[(size_t)NN * HC];
__device__ __half  g_hh  [(size_t)NN * 2 * CZ];
__device__ __half  g_WkvT[512 * DF];            // [c][j] = lw_j * W_jc (fp16)
__device__ __half  g_BT  [768 * 64];            // rows 0-511: W'e-slice; 512-767: WeT
__device__ float   g_c0  [512];                 // lb@W + bkv
__device__ float   g_c1  [512];                 // lw@W
__device__ __half  g_xh  [(size_t)NN * CZ];
__device__ __half  g_ph  [(size_t)NN * CZ];
__device__ __half  g_eah [(size_t)NE * CE];
__device__ float   g_sx[NN], g_qx[NN], g_sp[NN], g_qp[NN];
__device__ float   g_se[NE], g_qe[NE];
__device__ __half  g_wqT [HC * CZ];
__device__ __half  g_w1T [2 * CZ * CZ];
__device__ __half  g_w2T [CZ * 2 * CZ];
__device__ float   g_zeros[768];                // static zero-init (never written)

// ---------------- conversion pass --------------------------------------------
__global__ void k_cvt(const float* __restrict__ src, __half* __restrict__ dst, int n4) {
    int i = blockIdx.x * blockDim.x + threadIdx.x;
    if (i >= n4) return;
    float4 v = ((const float4*)src)[i];
    __half2 a = __floats2half2_rn(v.x, v.y);
    __half2 b = __floats2half2_rn(v.z, v.w);
    uint2 o; o.x = *(unsigned*)&a; o.y = *(unsigned*)&b;
    ((uint2*)dst)[i] = o;
}

// ------------- all weight prep in one kernel ---------------------------------
__global__ void k_prepW(const float* __restrict__ Wk, const float* __restrict__ Wv,
                        const float* __restrict__ lw, const float* __restrict__ lb,
                        const float* __restrict__ bk, const float* __restrict__ bv,
                        const float* __restrict__ Wq, const float* __restrict__ We,
                        const float* __restrict__ W1, const float* __restrict__ W2) {
    int i = blockIdx.x * blockDim.x + threadIdx.x;
    if (i < DF * 512) {
        int j = i >> 9, c = i & 511;
        float w = (c < 256) ? Wk[j * 256 + c] : Wv[j * 256 + (c - 256)];
        g_WkvT[(size_t)c * DF + j] = __float2half_rn(lw[j] * w);
    }
    if (i < 768 * 64) {         // merged EG B: [r][k]
        int r = i >> 6, k = i & 63;
        float w;
        if (r < 256)      w = lw[k] * Wk[k * 256 + r];
        else if (r < 512) w = lw[k] * Wv[k * 256 + (r - 256)];
        else              w = We[k * 256 + (r - 512)];
        g_BT[i] = __float2half_rn(w);
    }
    if (i < CZ * HC) {          // wqT
        int n = i >> 8, k = i & 255;
        g_wqT[n * 256 + k] = __float2half_rn(Wq[k * 256 + n]);
    }
    if (i < 512 * 256) {        // w1T[n(512)][k(256)] = W1[k][n]
        int n = i >> 8, k = i & 255;
        g_w1T[n * 256 + k] = __float2half_rn(W1[k * 512 + n]);
    }
    if (i < 256 * 512) {        // w2T[n(256)][k(512)] = W2[k][n]
        int n = i >> 9, k = i & 511;
        g_w2T[n * 512 + k] = __float2half_rn(W2[k * 256 + n]);
    }
    if (i < 512) {              // c1 = lw@W, c0 = lb@W + bkv
        int c = i;
        float s1 = 0.f, s0 = 0.f;
        for (int j = 0; j < DF; j++) {
            float w = (c < 256) ? Wk[j * 256 + c] : Wv[j * 256 + (c - 256)];
            s1 += lw[j] * w;
            s0 += lb[j] * w;
        }
        g_c1[c] = s1;
        g_c0[c] = s0 + ((c < 256) ? bk[c] : bv[c - 256]);
    }
}

// ------------- node+edge prep: sums, sumsq, fp16 copies, zeroing -------------
__global__ void k_pre(const float* __restrict__ x, const float* __restrict__ p,
                      const float* __restrict__ ea) {
    size_t gid = (size_t)blockIdx.x * 256 + threadIdx.x;
    if (gid < (size_t)NN * HC) g_attn[gid] = 0.f;
    if (gid < (size_t)NN * NH) g_ssum[gid] = 0.f;
    int w = blockIdx.x * 8 + (threadIdx.x >> 5);
    int lane = threadIdx.x & 31;
    if (w < NN) {
        const float* xr = x + (size_t)w * CZ;
        const float* pr = p + (size_t)w * CZ;
        float sxv = 0.f, qxv = 0.f, spv = 0.f, qpv = 0.f;
#pragma unroll
        for (int i = 0; i < 8; i++) {
            int j = lane + 32 * i;
            float vx = xr[j], vp = pr[j];
            sxv += vx; qxv += vx * vx;
            spv += vp; qpv += vp * vp;
            g_xh[(size_t)w * CZ + j] = __float2half_rn(vx);
            g_ph[(size_t)w * CZ + j] = __float2half_rn(vp);
        }
#pragma unroll
        for (int o = 16; o; o >>= 1) {
            sxv += __shfl_xor_sync(~0u, sxv, o);
            qxv += __shfl_xor_sync(~0u, qxv, o);
            spv += __shfl_xor_sync(~0u, spv, o);
            qpv += __shfl_xor_sync(~0u, qpv, o);
        }
        if (lane == 0) { g_sx[w] = sxv; g_qx[w] = qxv; g_sp[w] = spv; g_qp[w] = qpv; }
    } else if (w < NN + NE) {
        int e = w - NN;
        const float* er = ea + (size_t)e * CE;
        float v0 = er[lane], v1 = er[lane + 32];
        float s = v0 + v1, q = v0 * v0 + v1 * v1;
        g_eah[(size_t)e * CE + lane]      = __float2half_rn(v0);
        g_eah[(size_t)e * CE + lane + 32] = __float2half_rn(v1);
#pragma unroll
        for (int o = 16; o; o >>= 1) {
            s += __shfl_xor_sync(~0u, s, o);
            q += __shfl_xor_sync(~0u, q, o);
        }
        if (lane == 0) { g_se[e] = s; g_qe[e] = q; }
    }
}

// ================= fp16 GEMM 128x128x64, ldmatrix + swizzle, 3-stage =========
#define HT_STAGE 8192
#define HGEMM_SMEM (6 * HT_STAGE * 2)

__device__ __forceinline__ void cp16g(unsigned dst, const void* src, int sz) {
    asm volatile("cp.async.cg.shared.global [%0], [%1], 16, %2;\n"
                 :: "r"(dst), "l"(src), "r"(sz));
}
__device__ __forceinline__ void ldsm4(unsigned& r0, unsigned& r1, unsigned& r2,
                                      unsigned& r3, unsigned addr) {
    asm volatile("ldmatrix.sync.aligned.m8n8.x4.shared.b16 {%0,%1,%2,%3}, [%4];"
                 : "=r"(r0), "=r"(r1), "=r"(r2), "=r"(r3) : "r"(addr));
}
__device__ __forceinline__ void mma16816(float* c, const unsigned* a, const unsigned* b) {
    asm volatile(
        "mma.sync.aligned.m16n8k16.row.col.f32.f16.f16.f32 "
        "{%0,%1,%2,%3}, {%4,%5,%6,%7}, {%8,%9}, {%0,%1,%2,%3};\n"
        : "+f"(c[0]), "+f"(c[1]), "+f"(c[2]), "+f"(c[3])
        : "r"(a[0]), "r"(a[1]), "r"(a[2]), "r"(a[3]), "r"(b[0]), "r"(b[1]));
}

__global__ __launch_bounds__(256, 2) void hgemm(
    const __half* __restrict__ A, int lda,
    const __half* __restrict__ Bt, int ldb,
    const float* __restrict__ bias, void* __restrict__ Cv,
    int M, int N, int K, int act) {
    extern __shared__ __half smh[];
    int tid = threadIdx.x;
    int lane = tid & 31, wid = tid >> 5;
    int bm = blockIdx.y * 128, bn = blockIdx.x * 128;
    int wm = (wid >> 1) * 32;
    int wn = (wid & 1) * 64;
    int lm = lane >> 2, lq = lane & 3;

    unsigned asBase = (unsigned)__cvta_generic_to_shared(smh);
    unsigned bsBase = asBase + 3 * HT_STAGE * 2;

    int l7 = lane & 7;
    int rowA = lane & 15;
    int kcA  = lane >> 4;
    int rowB = (lane & 7) + ((lane & 16) ? 8 : 0);
    int kcB  = (lane >> 3) & 1;

    float acc[2][8][4];
#pragma unroll
    for (int i = 0; i < 2; i++)
#pragma unroll
        for (int j = 0; j < 8; j++)
#pragma unroll
            for (int q = 0; q < 4; q++) acc[i][j][q] = 0.f;

    int KT = K >> 6;

    auto load_stage = [&](int s, int k0) {
#pragma unroll
        for (int t = 0; t < 4; t++) {
            int c = tid + t * 256;
            int row = c >> 3, kc = c & 7;
            int ok = (bm + row < M) ? 16 : 0;
            cp16g(asBase + s * (HT_STAGE * 2) + row * 128 + ((kc ^ (row & 7)) << 4),
                  A + (size_t)(bm + row) * lda + k0 + kc * 8, ok);
        }
#pragma unroll
        for (int t = 0; t < 4; t++) {
            int c = tid + t * 256;
            int row = c >> 3, kc = c & 7;
            cp16g(bsBase + s * (HT_STAGE * 2) + row * 128 + ((kc ^ (row & 7)) << 4),
                  Bt + (size_t)(bn + row) * ldb + k0 + kc * 8, 16);
        }
        asm volatile("cp.async.commit_group;\n");
    };

    load_stage(0, 0);
    if (KT > 1) load_stage(1, 64);

    for (int kt = 0; kt < KT; kt++) {
        if (kt + 1 < KT) { asm volatile("cp.async.wait_group 1;\n"); }
        else             { asm volatile("cp.async.wait_group 0;\n"); }
        __syncthreads();
        if (kt + 2 < KT) load_stage((kt + 2) % 3, (kt + 2) * 64);
        int stage = kt % 3;
        unsigned aOff = asBase + stage * (HT_STAGE * 2);
        unsigned bOff = bsBase + stage * (HT_STAGE * 2);
#pragma unroll
        for (int ks = 0; ks < 4; ks++) {
            int kc = ks * 2;
            unsigned af[2][4], bf[8][2];
#pragma unroll
            for (int mt = 0; mt < 2; mt++) {
                unsigned addr = aOff + (wm + mt * 16 + rowA) * 128 +
                                (((kc + kcA) ^ l7) << 4);
                ldsm4(af[mt][0], af[mt][1], af[mt][2], af[mt][3], addr);
            }
#pragma unroll
            for (int ntp = 0; ntp < 4; ntp++) {
                unsigned addr = bOff + (wn + ntp * 16 + rowB) * 128 +
                                (((kc + kcB) ^ l7) << 4);
                ldsm4(bf[2 * ntp][0], bf[2 * ntp][1],
                      bf[2 * ntp + 1][0], bf[2 * ntp + 1][1], addr);
            }
#pragma unroll
            for (int mt = 0; mt < 2; mt++)
#pragma unroll
                for (int nt = 0; nt < 8; nt++)
                    mma16816(acc[mt][nt], af[mt], bf[nt]);
        }
    }

#pragma unroll
    for (int mt = 0; mt < 2; mt++) {
        int r0 = bm + wm + mt * 16 + lm;
        int r1 = r0 + 8;
#pragma unroll
        for (int nt = 0; nt < 8; nt++) {
            int c = bn + wn + nt * 8 + lq * 2;
            float b0 = bias[c], b1 = bias[c + 1];
            float v0 = acc[mt][nt][0] + b0, v1 = acc[mt][nt][1] + b1;
            float v2 = acc[mt][nt][2] + b0, v3 = acc[mt][nt][3] + b1;
            if (act & 1) {
                v0 = v0 / (1.f + expf(-v0)); v1 = v1 / (1.f + expf(-v1));
                v2 = v2 / (1.f + expf(-v2)); v3 = v3 / (1.f + expf(-v3));
            }
            if (act & 2) {
                __half* C = (__half*)Cv;
                __half2 h0 = __floats2half2_rn(v0, v1);
                __half2 h1 = __floats2half2_rn(v2, v3);
                if (r0 < M) *(__half2*)(C + (size_t)r0 * N + c) = h0;
                if (r1 < M) *(__half2*)(C + (size_t)r1 * N + c) = h1;
            } else {
                float* C = (float*)Cv;
                if (r0 < M) *(float2*)(C + (size_t)r0 * N + c) = make_float2(v0, v1);
                if (r1 < M) *(float2*)(C + (size_t)r1 * N + c) = make_float2(v2, v3);
            }
        }
    }
}

// ------- per-node score terms: QX = q.X'(khalf), QC1 = q.c1, QC0 = q.c0 ------
__global__ void k_qdots() {
    int n = blockIdx.x * 8 + (threadIdx.x >> 5);
    int lane = threadIdx.x & 31;
    if (n >= NN) return;
    int c = lane * 8;
    uint4 qv = *(const uint4*)(g_qh + (size_t)n * 256 + c);
    float2 q0 = __half22float2(*(const __half2*)&qv.x);
    float2 q1 = __half22float2(*(const __half2*)&qv.y);
    float2 q2 = __half22float2(*(const __half2*)&qv.z);
    float2 q3 = __half22float2(*(const __half2*)&qv.w);
    float4 xa = *(const float4*)(g_X + (size_t)n * 512 + c);
    float4 xb = *(const float4*)(g_X + (size_t)n * 512 + c + 4);
    float4 c1a = *(const float4*)(g_c1 + c);
    float4 c1b = *(const float4*)(g_c1 + c + 4);
    float4 c0a = *(const float4*)(g_c0 + c);
    float4 c0b = *(const float4*)(g_c0 + c + 4);
    float px  = q0.x * xa.x + q0.y * xa.y + q1.x * xa.z + q1.y * xa.w +
                q2.x * xb.x + q2.y * xb.y + q3.x * xb.z + q3.y * xb.w;
    float p1  = q0.x * c1a.x + q0.y * c1a.y + q1.x * c1a.z + q1.y * c1a.w +
                q2.x * c1b.x + q2.y * c1b.y + q3.x * c1b.z + q3.y * c1b.w;
    float p0  = q0.x * c0a.x + q0.y * c0a.y + q1.x * c0a.z + q1.y * c0a.w +
                q2.x * c0b.x + q2.y * c0b.y + q3.x * c0b.z + q3.y * c0b.w;
    px += __shfl_xor_sync(~0u, px, 1); px += __shfl_xor_sync(~0u, px, 2);
    p1 += __shfl_xor_sync(~0u, p1, 1); p1 += __shfl_xor_sync(~0u, p1, 2);
    p0 += __shfl_xor_sync(~0u, p0, 1); p0 += __shfl_xor_sync(~0u, p0, 2);
    if ((lane & 3) == 0) {
        int h = lane >> 2;
        g_QX [(size_t)n * 8 + h] = px;
        g_QC1[(size_t)n * 8 + h] = p1;
        g_QC0[(size_t)n * 8 + h] = p0;
    }
}

// ------- combine: LN reconstruction; scores (node-decomposed); w = v*eg ------
// persistent: warp per edge, grid-stride.
__global__ __launch_bounds__(256) void k_combine(const int* __restrict__ ei) {
    __shared__ float c0s[512], c1s[512];
    int tid = threadIdx.x;
    c0s[tid] = g_c0[tid]; c0s[tid + 256] = g_c0[tid + 256];
    c1s[tid] = g_c1[tid]; c1s[tid + 256] = g_c1[tid + 256];
    __syncthreads();
    int lane = tid & 31, wid = tid >> 5;
    int c = lane * 8;
    int stride = gridDim.x * 8;
    for (int e = blockIdx.x * 8 + wid; e < NE; e += stride) {
        int s = ei[e], d = ei[NE + e];
        float mu   = (g_se[e] + g_sx[s] + g_sp[d]) * (1.f / 576.f);
        float ms   = (g_qe[e] + g_qx[s] + g_qp[d]) * (1.f / 576.f);
        float rstd = rsqrtf(ms - mu * mu + LN_EPS);
        float a1   = -rstd * mu;
        const __half* EG = g_EG + (size_t)e * 768;
        // ---- k half: score = (rstd*(q.E' + q.P' + QX) + a1*QC1 + QC0)/sqrt(32)
        {
            uint4 eh = *(const uint4*)(EG + c);
            float2 e0 = __half22float2(*(const __half2*)&eh.x);
            float2 e1 = __half22float2(*(const __half2*)&eh.y);
            float2 e2 = __half22float2(*(const __half2*)&eh.z);
            float2 e3 = __half22float2(*(const __half2*)&eh.w);
            float4 pa = *(const float4*)(g_P + (size_t)d * 512 + c);
            float4 pb = *(const float4*)(g_P + (size_t)d * 512 + c + 4);
            uint4 qv = *(const uint4*)(g_qh + (size_t)s * 256 + c);
            float2 q0 = __half22float2(*(const __half2*)&qv.x);
            float2 q1 = __half22float2(*(const __half2*)&qv.y);
            float2 q2 = __half22float2(*(const __half2*)&qv.z);
            float2 q3 = __half22float2(*(const __half2*)&qv.w);
            float part = q0.x * (e0.x + pa.x) + q0.y * (e0.y + pa.y) +
                         q1.x * (e1.x + pa.z) + q1.y * (e1.y + pa.w) +
                         q2.x * (e2.x + pb.x) + q2.y * (e2.y + pb.y) +
                         q3.x * (e3.x + pb.z) + q3.y * (e3.y + pb.w);
            part += __shfl_xor_sync(~0u, part, 1);
            part += __shfl_xor_sync(~0u, part, 2);
            if ((lane & 3) == 0) {
                int h = lane >> 2;
                float qk = rstd * (part + g_QX[(size_t)s * 8 + h]) +
                           a1 * g_QC1[(size_t)s * 8 + h] + g_QC0[(size_t)s * 8 + h];
                float ex = expf(qk * 0.17677669529663687f);
                g_sc[(size_t)e * 8 + h] = ex;
                atomicAdd(&g_ssum[(size_t)s * 8 + h], ex);
            }
        }
        // ---- v half (channels 256+c..): w = v * eg -> fp16 ----
        {
            int c2 = 256 + c;
            uint4 eh = *(const uint4*)(EG + c2);
            float2 e0 = __half22float2(*(const __half2*)&eh.x);
            float2 e1 = __half22float2(*(const __half2*)&eh.y);
            float2 e2 = __half22float2(*(const __half2*)&eh.z);
            float2 e3 = __half22float2(*(const __half2*)&eh.w);
            float4 xa = *(const float4*)(g_X + (size_t)s * 512 + c2);
            float4 xb = *(const float4*)(g_X + (size_t)s * 512 + c2 + 4);
            float4 pa = *(const float4*)(g_P + (size_t)d * 512 + c2);
            float4 pb = *(const float4*)(g_P + (size_t)d * 512 + c2 + 4);
            float4 c1a = *(const float4*)&c1s[c2];
            float4 c1b = *(const float4*)&c1s[c2 + 4];
            float4 c0a = *(const float4*)&c0s[c2];
            float4 c0b = *(const float4*)&c0s[c2 + 4];
            float v0 = rstd * (e0.x + xa.x + pa.x) + a1 * c1a.x + c0a.x;
            float v1 = rstd * (e0.y + xa.y + pa.y) + a1 * c1a.y + c0a.y;
            float v2 = rstd * (e1.x + xa.z + pa.z) + a1 * c1a.z + c0a.z;
            float v3 = rstd * (e1.y + xa.w + pa.w) + a1 * c1a.w + c0a.w;
            float v4 = rstd * (e2.x + xb.x + pb.x) + a1 * c1b.x + c0b.x;
            float v5 = rstd * (e2.y + xb.y + pb.y) + a1 * c1b.y + c0b.y;
            float v6 = rstd * (e3.x + xb.z + pb.z) + a1 * c1b.z + c0b.z;
            float v7 = rstd * (e3.y + xb.w + pb.w) + a1 * c1b.w + c0b.w;
            uint4 gh = *(const uint4*)(EG + 512 + c);
            float2 g0 = __half22float2(*(const __half2*)&gh.x);
            float2 g1 = __half22float2(*(const __half2*)&gh.y);
            float2 g2 = __half22float2(*(const __half2*)&gh.z);
            float2 g3 = __half22float2(*(const __half2*)&gh.w);
            __half2 w0 = __floats2half2_rn(v0 * g0.x, v1 * g0.y);
            __half2 w1 = __floats2half2_rn(v2 * g1.x, v3 * g1.y);
            __half2 w2 = __floats2half2_rn(v4 * g2.x, v5 * g2.y);
            __half2 w3 = __floats2half2_rn(v6 * g3.x, v7 * g3.y);
            uint4 o;
            o.x = *(unsigned*)&w0; o.y = *(unsigned*)&w1;
            o.z = *(unsigned*)&w2; o.w = *(unsigned*)&w3;
            *(uint4*)(g_wh + (size_t)e * 256 + c) = o;
        }
    }
}

// ---------------- scatter: m = alpha * w, vector reductions ------------------
__global__ __launch_bounds__(256) void k_scatter(const int* __restrict__ ei) {
    int e = (blockIdx.x * blockDim.x + threadIdx.x) >> 5;
    int lane = threadIdx.x & 31;
    if (e >= NE) return;
    int s = ei[e];
    int h = lane >> 2;
    float alpha = g_sc[(size_t)e * 8 + h] * __frcp_rn(g_ssum[(size_t)s * 8 + h]);
    const uint4 ww = *(const uint4*)(g_wh + (size_t)e * 256 + lane * 8);
    float2 w0 = __half22float2(*(const __half2*)&ww.x);
    float2 w1 = __half22float2(*(const __half2*)&ww.y);
    float2 w2 = __half22float2(*(const __half2*)&ww.z);
    float2 w3 = __half22float2(*(const __half2*)&ww.w);
    float m0 = alpha * w0.x, m1 = alpha * w0.y;
    float m2 = alpha * w1.x, m3 = alpha * w1.y;
    float m4 = alpha * w2.x, m5 = alpha * w2.y;
    float m6 = alpha * w3.x, m7 = alpha * w3.y;
    float* dst = g_attn + (size_t)s * 256 + lane * 8;
    asm volatile("red.global.add.v4.f32 [%0], {%1,%2,%3,%4};"
                 :: "l"(dst), "f"(m0), "f"(m1), "f"(m2), "f"(m3) : "memory");
    asm volatile("red.global.add.v4.f32 [%0], {%1,%2,%3,%4};"
                 :: "l"(dst + 4), "f"(m4), "f"(m5), "f"(m6), "f"(m7) : "memory");
}

// ---------------- launch -----------------------------------------------------
extern "C" void kernel_launch(void* const* d_in, const int* in_sizes, int n_in,
                              void* d_out, int out_size) {
    const float* x  = (const float*)d_in[0];
    const float* p  = (const float*)d_in[1];
    const float* ea = (const float*)d_in[2];
    const int*   ei = (const int*)  d_in[3];
    const float* lw = (const float*)d_in[4];
    const float* lb = (const float*)d_in[5];
    const float* Wq = (const float*)d_in[6];
    const float* bq = (const float*)d_in[7];
    const float* Wk = (const float*)d_in[8];
    const float* bk = (const float*)d_in[9];
    const float* Wv = (const float*)d_in[10];
    const float* bv = (const float*)d_in[11];
    const float* We = (const float*)d_in[12];
    const float* W1 = (const float*)d_in[13];
    const float* b1 = (const float*)d_in[14];
    const float* W2 = (const float*)d_in[15];
    const float* b2 = (const float*)d_in[16];
    float* out = (float*)d_out;

    void *pX, *pP, *pEG, *pQh, *pAttn, *pAttnH, *pHh;
    void *pWkvT, *pBT, *pXh, *pPh, *pEah, *pWqT, *pW1T, *pW2T, *pZeros;
    cudaGetSymbolAddress(&pX,     g_X);
    cudaGetSymbolAddress(&pP,     g_P);
    cudaGetSymbolAddress(&pEG,    g_EG);
    cudaGetSymbolAddress(&pQh,    g_qh);
    cudaGetSymbolAddress(&pAttn,  g_attn);
    cudaGetSymbolAddress(&pAttnH, g_attnh);
    cudaGetSymbolAddress(&pHh,    g_hh);
    cudaGetSymbolAddress(&pWkvT,  g_WkvT);
    cudaGetSymbolAddress(&pBT,    g_BT);
    cudaGetSymbolAddress(&pXh,    g_xh);
    cudaGetSymbolAddress(&pPh,    g_ph);
    cudaGetSymbolAddress(&pEah,   g_eah);
    cudaGetSymbolAddress(&pWqT,   g_wqT);
    cudaGetSymbolAddress(&pW1T,   g_w1T);
    cudaGetSymbolAddress(&pW2T,   g_w2T);
    cudaGetSymbolAddress(&pZeros, g_zeros);

    cudaFuncSetAttribute(hgemm, cudaFuncAttributeMaxDynamicSharedMemorySize, HGEMM_SMEM);

    // 1: prep nodes/edges (sums + fp16 copies + zero attn/ssum)
    k_pre<<<(NN + NE + 7) / 8, 256>>>(x, p, ea);
    // 2: all weight prep
    k_prepW<<<(DF * 512 + 255) / 256, 256>>>(Wk, Wv, lw, lb, bk, bv, Wq, We, W1, W2);
    // 3: q = x @ Wq + bq (fp16)
    {
        dim3 g(HC / 128, (NN + 127) / 128);
        hgemm<<<g, 256, HGEMM_SMEM>>>((const __half*)pXh, CZ,
                                      (const __half*)pWqT, CZ, bq, pQh, NN, HC, CZ, 2);
    }
    // 4,5: X' and P' (fp32)
    {
        dim3 g(512 / 128, (NN + 127) / 128);
        hgemm<<<g, 256, HGEMM_SMEM>>>((const __half*)pXh, CZ,
                                      (const __half*)pWkvT + 64, DF,
                                      (const float*)pZeros, pX, NN, 512, CZ, 0);
        hgemm<<<g, 256, HGEMM_SMEM>>>((const __half*)pPh, CZ,
                                      (const __half*)pWkvT + 320, DF,
                                      (const float*)pZeros, pP, NN, 512, CZ, 0);
    }
    // 6: merged EG = ea @ [W'e | We] (fp16 out, N=768)
    {
        dim3 g(768 / 128, NE / 128);
        hgemm<<<g, 256, HGEMM_SMEM>>>((const __half*)pEah, CE,
                                      (const __half*)pBT, CE,
                                      (const float*)pZeros, pEG, NE, 768, CE, 2);
    }
    // 7: per-node score terms
    k_qdots<<<(NN + 7) / 8, 256>>>();
    // 8: combine (persistent): scores + w = v*eg
    k_combine<<<1184, 256>>>(ei);
    // 9: scatter
    k_scatter<<<(NE * 32 + 255) / 256, 256>>>(ei);
    // 10: attn -> fp16
    k_cvt<<<(NN * HC / 4 + 255) / 256, 256>>>((const float*)pAttn, (__half*)pAttnH, NN * HC / 4);
    // 11,12: MLP
    {
        dim3 g1(512 / 128, (NN + 127) / 128);
        hgemm<<<g1, 256, HGEMM_SMEM>>>((const __half*)pAttnH, CZ,
                                       (const __half*)pW1T, CZ, b1, pHh, NN, 512, CZ, 3);
        dim3 g2(HC / 128, (NN + 127) / 128);
        hgemm<<<g2, 256, HGEMM_SMEM>>>((const __half*)pHh, 2 * CZ,
                                       (const __half*)pW2T, 2 * CZ, b2, out, NN, HC, 2 * CZ, 0);
    }
}